// round 9
// baseline (speedup 1.0000x reference)
#include <cuda_runtime.h>
#include <cuda_bf16.h>
#include <math.h>
#include <stdint.h>

#define Bb   2
#define Ss   2048
#define Dd   2048
#define Hh   16
#define KVHh 4
#define HDd  128
#define NQKV 3072      // 2048 q + 512 k + 512 v

typedef __nv_bfloat16 bf16;

// ---------------- scratch (static device globals; no allocs) ----------------
__device__ float g_qkv[Bb * Ss * NQKV];        // fused qkv proj output, 50 MB
__device__ float g_cos[Ss * 64];
__device__ float g_sin[Ss * 64];
// split-bf16 operands. xh/xl: x-split -> Q-split (post) -> attn-out-split (flash)
__device__ __align__(16) bf16 g_xh[Bb * Ss * Dd];
__device__ __align__(16) bf16 g_xl[Bb * Ss * Dd];
__device__ __align__(16) bf16 g_wh[NQKV * Dd];
__device__ __align__(16) bf16 g_wl[NQKV * Dd];
__device__ __align__(16) bf16 g_kh[Bb * Ss * KVHh * HDd];
__device__ __align__(16) bf16 g_kl[Bb * Ss * KVHh * HDd];
__device__ __align__(16) bf16 g_vh[Bb * Ss * KVHh * HDd];
__device__ __align__(16) bf16 g_vl[Bb * Ss * KVHh * HDd];

// ---------------- helpers ----------------------------------------------------
__device__ __forceinline__ uint32_t smem_u32(const void* p) {
    uint32_t a;
    asm("{ .reg .u64 t; cvta.to.shared.u64 t, %1; cvt.u32.u64 %0, t; }" : "=r"(a) : "l"(p));
    return a;
}
#define CP_ASYNC16(dst, src) \
    asm volatile("cp.async.cg.shared.global [%0], [%1], 16;" :: "r"(dst), "l"(src) : "memory")
#define CP_COMMIT()  asm volatile("cp.async.commit_group;" ::: "memory")
#define CP_WAIT0()   asm volatile("cp.async.wait_group 0;" ::: "memory")

__device__ __forceinline__ void mma16816(float* d, const uint32_t* a, const uint32_t* b) {
    asm volatile("mma.sync.aligned.m16n8k16.row.col.f32.bf16.bf16.f32 "
        "{%0,%1,%2,%3}, {%4,%5,%6,%7}, {%8,%9}, {%0,%1,%2,%3};"
        : "+f"(d[0]), "+f"(d[1]), "+f"(d[2]), "+f"(d[3])
        : "r"(a[0]), "r"(a[1]), "r"(a[2]), "r"(a[3]), "r"(b[0]), "r"(b[1]));
}
__device__ __forceinline__ void ldsm4(uint32_t* r, uint32_t a) {
    asm volatile("ldmatrix.sync.aligned.m8n8.x4.shared.b16 {%0,%1,%2,%3}, [%4];"
        : "=r"(r[0]), "=r"(r[1]), "=r"(r[2]), "=r"(r[3]) : "r"(a));
}
#define LDSM4T(r, a) \
    asm volatile("ldmatrix.sync.aligned.m8n8.x4.trans.shared.b16 {%0,%1,%2,%3}, [%4];" \
        : "=r"((r)[0]), "=r"((r)[1]), "=r"((r)[2]), "=r"((r)[3]) : "r"(a))

// pack two fp32 into bf16x2 (hi) and their residuals into bf16x2 (lo)
__device__ __forceinline__ void splitpk(float x0, float x1, uint32_t& hi, uint32_t& lo) {
    bf16 h0 = __float2bfloat16(x0), h1 = __float2bfloat16(x1);
    __nv_bfloat162 th = __halves2bfloat162(h0, h1);
    hi = *(uint32_t*)&th;
    bf16 r0 = __float2bfloat16(x0 - __bfloat162float(h0));
    bf16 r1 = __float2bfloat16(x1 - __bfloat162float(h1));
    __nv_bfloat162 tl = __halves2bfloat162(r0, r1);
    lo = *(uint32_t*)&tl;
}

// ---------------- RoPE table ------------------------------------------------
__global__ void rope_table_kernel() {
    int i = blockIdx.x * blockDim.x + threadIdx.x;
    if (i >= Ss * 64) return;
    int s = i >> 6, j = i & 63;
    float e   = (float)(2 * j) / (float)HDd;
    float inv = 1.0f / powf(10000.0f, e);
    float ang = (float)s * inv;
    g_cos[i] = (float)cos((double)ang);
    g_sin[i] = (float)sin((double)ang);
}

// ---------------- fp32 -> bf16 hi/lo split ----------------------------------
__global__ __launch_bounds__(256) void cvt_split(const float* __restrict__ src,
                                                 bf16* __restrict__ hi,
                                                 bf16* __restrict__ lo, int n4) {
    int i = blockIdx.x * blockDim.x + threadIdx.x;
    if (i >= n4) return;
    float4 v = ((const float4*)src)[i];
    uint32_t h0, l0, h1, l1;
    splitpk(v.x, v.y, h0, l0);
    splitpk(v.z, v.w, h1, l1);
    ((uint32_t*)hi)[2 * i] = h0; ((uint32_t*)hi)[2 * i + 1] = h1;
    ((uint32_t*)lo)[2 * i] = l0; ((uint32_t*)lo)[2 * i + 1] = l1;
}

// ---------------- split-bf16 HMMA GEMM: C = A @ B^T -------------------------
// A:[M,K], B:[N,K] row-major bf16 hi/lo. CTA tile 128x128, K-chunk 32,
// 8 warps 2(M)x4(N), warp tile 64x32. ldmatrix fragment loads, 3-pass terms.
#define LDA        40
#define ARRB       (128 * LDA * 2)          // 10240 B per operand array
#define STAGEB     (4 * ARRB)               // 40960 B per stage
#define GEMM_SMEM  (2 * STAGEB)             // 81920 B

__device__ __forceinline__ void gemm_load_chunk(
    uint32_t sm32, int buf, int tid, int c,
    const bf16* __restrict__ Ah, const bf16* __restrict__ Al,
    const bf16* __restrict__ Bh, const bf16* __restrict__ Bl,
    int bm, int bn, int K) {
    int row = tid >> 2;
    int t16 = tid & 3;
    uint32_t so = sm32 + buf * STAGEB + (uint32_t)row * 80 + (uint32_t)t16 * 16;
    size_t gA = (size_t)(bm + row) * K + (size_t)c * 32 + t16 * 8;
    size_t gB = (size_t)(bn + row) * K + (size_t)c * 32 + t16 * 8;
    size_t stp = (size_t)64 * K;
    CP_ASYNC16(so,                       Ah + gA);
    CP_ASYNC16(so + 64 * 80,             Ah + gA + stp);
    CP_ASYNC16(so + ARRB,                Al + gA);
    CP_ASYNC16(so + ARRB + 64 * 80,      Al + gA + stp);
    CP_ASYNC16(so + 2 * ARRB,            Bh + gB);
    CP_ASYNC16(so + 2 * ARRB + 64 * 80,  Bh + gB + stp);
    CP_ASYNC16(so + 3 * ARRB,            Bl + gB);
    CP_ASYNC16(so + 3 * ARRB + 64 * 80,  Bl + gB + stp);
}

__global__ __launch_bounds__(256, 2) void gemm_bf16s(
    const bf16* __restrict__ Ah, const bf16* __restrict__ Al,
    const bf16* __restrict__ Bh, const bf16* __restrict__ Bl,
    float* __restrict__ C, int M, int N, int K) {
    extern __shared__ char sm[];
    const uint32_t sm32 = smem_u32(sm);
    const int tid  = threadIdx.x;
    const int wid  = tid >> 5, lane = tid & 31;
    const int lr   = lane >> 2, lc = lane & 3;
    const int lm   = lane & 15, lk2 = lane >> 4;
    const int wm   = wid & 1;
    const int wn   = wid >> 1;
    const int bm = blockIdx.y * 128, bn = blockIdx.x * 128;

    float acc[4][4][4];
#pragma unroll
    for (int i = 0; i < 4; i++)
#pragma unroll
        for (int j = 0; j < 4; j++)
#pragma unroll
            for (int r = 0; r < 4; r++) acc[i][j][r] = 0.0f;

    const int NC = K >> 5;
    gemm_load_chunk(sm32, 0, tid, 0, Ah, Al, Bh, Bl, bm, bn, K);
    CP_COMMIT();

    for (int c = 0; c < NC; c++) {
        CP_WAIT0();
        __syncthreads();
        if (c + 1 < NC) {
            gemm_load_chunk(sm32, (c + 1) & 1, tid, c + 1, Ah, Al, Bh, Bl, bm, bn, K);
            CP_COMMIT();
        }
        const uint32_t sbase = sm32 + (c & 1) * STAGEB;
        const uint32_t aad = sbase + (uint32_t)(wm * 64 + lm) * 80 + lk2 * 16;
        const uint32_t bad = sbase + 2 * ARRB + (uint32_t)(wn * 32 + lm) * 80 + lk2 * 16;
#pragma unroll
        for (int kst = 0; kst < 2; kst++) {
            const uint32_t koff = kst * 32;
            uint32_t ah[4][4], al[4][4], bh[2][4], bl[2][4];
#pragma unroll
            for (int mt = 0; mt < 4; mt++) {
                ldsm4(ah[mt], aad + mt * 1280 + koff);
                ldsm4(al[mt], aad + ARRB + mt * 1280 + koff);
            }
#pragma unroll
            for (int p = 0; p < 2; p++) {
                ldsm4(bh[p], bad + p * 1280 + koff);
                ldsm4(bl[p], bad + ARRB + p * 1280 + koff);
            }
            // pass 1: Ah*Bh
#pragma unroll
            for (int mt = 0; mt < 4; mt++)
#pragma unroll
                for (int nt = 0; nt < 4; nt++) {
                    uint32_t bf[2] = { bh[nt >> 1][nt & 1], bh[nt >> 1][(nt & 1) + 2] };
                    mma16816(acc[mt][nt], ah[mt], bf);
                }
            // pass 2: Ah*Bl
#pragma unroll
            for (int mt = 0; mt < 4; mt++)
#pragma unroll
                for (int nt = 0; nt < 4; nt++) {
                    uint32_t bf[2] = { bl[nt >> 1][nt & 1], bl[nt >> 1][(nt & 1) + 2] };
                    mma16816(acc[mt][nt], ah[mt], bf);
                }
            // pass 3: Al*Bh
#pragma unroll
            for (int mt = 0; mt < 4; mt++)
#pragma unroll
                for (int nt = 0; nt < 4; nt++) {
                    uint32_t bf[2] = { bh[nt >> 1][nt & 1], bh[nt >> 1][(nt & 1) + 2] };
                    mma16816(acc[mt][nt], al[mt], bf);
                }
        }
    }
    __syncthreads();

#pragma unroll
    for (int mt = 0; mt < 4; mt++) {
        int m = bm + wm * 64 + mt * 16 + lr;
#pragma unroll
        for (int nt = 0; nt < 4; nt++) {
            int n = bn + wn * 32 + nt * 8 + lc * 2;
            *(float2*)(C + (size_t)m * N + n)       = make_float2(acc[mt][nt][0], acc[mt][nt][1]);
            *(float2*)(C + (size_t)(m + 8) * N + n) = make_float2(acc[mt][nt][2], acc[mt][nt][3]);
        }
    }
}

// ---------------- q/kv epilogues: RMSNorm + RoPE (+gain) -> bf16 hi/lo ------
__global__ __launch_bounds__(256) void q_post(const float* __restrict__ gain,
                                              bf16* __restrict__ qh, bf16* __restrict__ ql) {
    int wid  = blockIdx.x * 8 + (threadIdx.x >> 5);   // 0..B*S*H-1
    int lane = threadIdx.x & 31;
    int h = wid & (Hh - 1);
    int row = wid >> 4;
    int s = row & (Ss - 1);
    const float* base = g_qkv + (size_t)row * NQKV + h * HDd;
    float e0 = base[lane], e1 = base[lane + 32], e2 = base[lane + 64], e3 = base[lane + 96];
    float ssum = e0 * e0 + e1 * e1 + e2 * e2 + e3 * e3;
#pragma unroll
    for (int o = 16; o > 0; o >>= 1) ssum += __shfl_xor_sync(0xffffffffu, ssum, o);
    float r = rsqrtf(ssum * (1.0f / 128.0f) + 1e-6f);
    float g = gain[h] * r * 0.08838834764831845f;
    float c0 = g_cos[s * 64 + lane],      sn0 = g_sin[s * 64 + lane];
    float c1 = g_cos[s * 64 + lane + 32], sn1 = g_sin[s * 64 + lane + 32];
    float o0 = ( e0 * c0  + e2 * sn0) * g;
    float o1 = ( e1 * c1  + e3 * sn1) * g;
    float o2 = (-e0 * sn0 + e2 * c0 ) * g;
    float o3 = (-e1 * sn1 + e3 * c1 ) * g;
    size_t off = (size_t)wid * 128;
    bf16 h0 = __float2bfloat16(o0); qh[off + lane]      = h0; ql[off + lane]      = __float2bfloat16(o0 - __bfloat162float(h0));
    bf16 h1 = __float2bfloat16(o1); qh[off + lane + 32] = h1; ql[off + lane + 32] = __float2bfloat16(o1 - __bfloat162float(h1));
    bf16 h2 = __float2bfloat16(o2); qh[off + lane + 64] = h2; ql[off + lane + 64] = __float2bfloat16(o2 - __bfloat162float(h2));
    bf16 h3 = __float2bfloat16(o3); qh[off + lane + 96] = h3; ql[off + lane + 96] = __float2bfloat16(o3 - __bfloat162float(h3));
}

__global__ __launch_bounds__(256) void kv_post(bf16* __restrict__ kh, bf16* __restrict__ kl,
                                               bf16* __restrict__ vh, bf16* __restrict__ vl) {
    int wid  = blockIdx.x * 8 + (threadIdx.x >> 5);   // 0..B*S*KVH-1
    int lane = threadIdx.x & 31;
    int kvh = wid & 3;
    int row = wid >> 2;
    int s = row & (Ss - 1);
    const float* kb = g_qkv + (size_t)row * NQKV + 2048 + kvh * HDd;
    const float* vb = kb + 512;
    // k: rmsnorm + rope + split
    float e0 = kb[lane], e1 = kb[lane + 32], e2 = kb[lane + 64], e3 = kb[lane + 96];
    float ssum = e0 * e0 + e1 * e1 + e2 * e2 + e3 * e3;
#pragma unroll
    for (int o = 16; o > 0; o >>= 1) ssum += __shfl_xor_sync(0xffffffffu, ssum, o);
    float r = rsqrtf(ssum * (1.0f / 128.0f) + 1e-6f);
    float c0 = g_cos[s * 64 + lane],      sn0 = g_sin[s * 64 + lane];
    float c1 = g_cos[s * 64 + lane + 32], sn1 = g_sin[s * 64 + lane + 32];
    float o0 = ( e0 * c0  + e2 * sn0) * r;
    float o1 = ( e1 * c1  + e3 * sn1) * r;
    float o2 = (-e0 * sn0 + e2 * c0 ) * r;
    float o3 = (-e1 * sn1 + e3 * c1 ) * r;
    size_t off = (size_t)wid * 128;
    bf16 h0 = __float2bfloat16(o0); kh[off + lane]      = h0; kl[off + lane]      = __float2bfloat16(o0 - __bfloat162float(h0));
    bf16 h1 = __float2bfloat16(o1); kh[off + lane + 32] = h1; kl[off + lane + 32] = __float2bfloat16(o1 - __bfloat162float(h1));
    bf16 h2 = __float2bfloat16(o2); kh[off + lane + 64] = h2; kl[off + lane + 64] = __float2bfloat16(o2 - __bfloat162float(h2));
    bf16 h3 = __float2bfloat16(o3); kh[off + lane + 96] = h3; kl[off + lane + 96] = __float2bfloat16(o3 - __bfloat162float(h3));
    // v: plain split
#pragma unroll
    for (int j = 0; j < 4; j++) {
        float f = vb[lane + 32 * j];
        bf16 fh = __float2bfloat16(f);
        vh[off + lane + 32 * j] = fh;
        vl[off + lane + 32 * j] = __float2bfloat16(f - __bfloat162float(fh));
    }
}

// ---------------- HMMA flash attention (split-bf16, BM=128, 8 warps) --------
#define FST  136
#define FBM  128
#define FQE  (FBM * FST)           // 17408 elems
#define FKE  (64 * FST)            // 8704 elems
#define FL2_SMEM ((2 * FQE + 2 * 4 * FKE) * 2)   // 208896 bytes

__device__ __forceinline__ void fl_load_kv(uint32_t sbase, int tid, int b, int kvh, int k0,
    const bf16* __restrict__ Kh, const bf16* __restrict__ Kl,
    const bf16* __restrict__ Vh, const bf16* __restrict__ Vl) {
#pragma unroll
    for (int it = 0; it < 4; it++) {
        int c = tid + it * 256;
        int r = c >> 4, o16 = c & 15;
        uint32_t d = sbase + (uint32_t)r * (FST * 2) + o16 * 16;
        size_t g = ((size_t)((b * Ss + k0 + r) * KVHh + kvh)) * HDd + o16 * 8;
        CP_ASYNC16(d,               Kh + g);
        CP_ASYNC16(d + 2 * FKE,     Kl + g);
        CP_ASYNC16(d + 4 * FKE,     Vh + g);
        CP_ASYNC16(d + 6 * FKE,     Vl + g);
    }
}

__global__ __launch_bounds__(256) void flash2(
    const bf16* __restrict__ Qh, const bf16* __restrict__ Ql,
    const bf16* __restrict__ Kh, const bf16* __restrict__ Kl,
    const bf16* __restrict__ Vh, const bf16* __restrict__ Vl,
    bf16* __restrict__ Oh, bf16* __restrict__ Ol) {
    extern __shared__ bf16 smb[];
    const uint32_t sm32 = smem_u32(smb);
    const int tid = threadIdx.x, wid = tid >> 5, lane = tid & 31;
    const int lr = lane >> 2, lc = lane & 3;
    const int lm = lane & 15, lk2 = lane >> 4;
    const int qtl = (Ss / FBM - 1) - blockIdx.x;    // big tiles first
    const int h = blockIdx.y, b = blockIdx.z, kvh = h >> 2;
    const int q0 = qtl * FBM;
    const int kend = 2 * qtl + 1;
    const int wrow = wid * 16;

    // Q tile (128 x 128) hi/lo -> smem
#pragma unroll
    for (int it = 0; it < 8; it++) {
        int c = tid + it * 256;
        int r = c >> 4, o = (c & 15) * 8;
        size_t g = (size_t)(b * Ss + q0 + r) * Dd + h * HDd + o;
        *(uint4*)(smb + r * FST + o)       = *(const uint4*)(Qh + g);
        *(uint4*)(smb + FQE + r * FST + o) = *(const uint4*)(Ql + g);
    }
    fl_load_kv(sm32 + 4 * FQE, tid, b, kvh, 0, Kh, Kl, Vh, Vl);
    CP_COMMIT();

    float m0 = -1e30f, m1 = -1e30f, l0 = 0.0f, l1 = 0.0f;
    float O[16][4];
#pragma unroll
    for (int i = 0; i < 16; i++) { O[i][0] = O[i][1] = O[i][2] = O[i][3] = 0.0f; }

    for (int kt = 0; kt <= kend; kt++) {
        const int stage = kt & 1;
        CP_WAIT0();
        __syncthreads();
        if (kt < kend) {
            fl_load_kv(sm32 + 4 * FQE + (stage ^ 1) * 8 * FKE, tid, b, kvh, (kt + 1) * 64,
                       Kh, Kl, Vh, Vl);
            CP_COMMIT();
        }

        const uint32_t kbase = sm32 + 4 * FQE + stage * 8 * FKE;
        const uint32_t vh32  = kbase + 4 * FKE;
        const uint32_t vl32  = kbase + 6 * FKE;

        // ---- S = Q . K^T (3-term split, ldmatrix frags) ----
        float S[8][4];
#pragma unroll
        for (int nt = 0; nt < 8; nt++) S[nt][0] = S[nt][1] = S[nt][2] = S[nt][3] = 0.0f;

        const uint32_t qadr = sm32 + (uint32_t)(wrow + lm) * (FST * 2) + lk2 * 16;
        const uint32_t badr = kbase + (uint32_t)lm * (FST * 2) + lk2 * 16;
#pragma unroll
        for (int kst = 0; kst < 8; kst++) {
            const uint32_t koff = kst * 32;
            uint32_t qh4[4], ql4[4], bh[4][4], blo[4][4];
            ldsm4(qh4, qadr + koff);
            ldsm4(ql4, qadr + 2 * FQE + koff);
#pragma unroll
            for (int p = 0; p < 4; p++) {
                ldsm4(bh[p],  badr + p * 16 * (FST * 2) + koff);
                ldsm4(blo[p], badr + 2 * FKE + p * 16 * (FST * 2) + koff);
            }
#pragma unroll
            for (int nt = 0; nt < 8; nt++) {
                uint32_t bf[2] = { bh[nt >> 1][nt & 1], bh[nt >> 1][(nt & 1) + 2] };
                mma16816(S[nt], qh4, bf);
            }
#pragma unroll
            for (int nt = 0; nt < 8; nt++) {
                uint32_t bf[2] = { blo[nt >> 1][nt & 1], blo[nt >> 1][(nt & 1) + 2] };
                mma16816(S[nt], qh4, bf);
            }
#pragma unroll
            for (int nt = 0; nt < 8; nt++) {
                uint32_t bf[2] = { bh[nt >> 1][nt & 1], bh[nt >> 1][(nt & 1) + 2] };
                mma16816(S[nt], ql4, bf);
            }
        }

        if (kt >= kend - 1) {   // tiles intersecting the diagonal: mask col > row
            const int row0 = q0 + wrow + lr;
#pragma unroll
            for (int nt = 0; nt < 8; nt++) {
                const int col = kt * 64 + nt * 8 + lc * 2;
                if (col     > row0)     S[nt][0] = -1e30f;
                if (col + 1 > row0)     S[nt][1] = -1e30f;
                if (col     > row0 + 8) S[nt][2] = -1e30f;
                if (col + 1 > row0 + 8) S[nt][3] = -1e30f;
            }
        }

        // ---- online softmax ----
        float rm0 = -1e30f, rm1 = -1e30f;
#pragma unroll
        for (int nt = 0; nt < 8; nt++) {
            rm0 = fmaxf(rm0, fmaxf(S[nt][0], S[nt][1]));
            rm1 = fmaxf(rm1, fmaxf(S[nt][2], S[nt][3]));
        }
        rm0 = fmaxf(rm0, __shfl_xor_sync(0xffffffffu, rm0, 1));
        rm0 = fmaxf(rm0, __shfl_xor_sync(0xffffffffu, rm0, 2));
        rm1 = fmaxf(rm1, __shfl_xor_sync(0xffffffffu, rm1, 1));
        rm1 = fmaxf(rm1, __shfl_xor_sync(0xffffffffu, rm1, 2));
        float mn0 = fmaxf(m0, rm0), mn1 = fmaxf(m1, rm1);
        float a0 = __expf(m0 - mn0), a1 = __expf(m1 - mn1);
        float rs0 = 0.0f, rs1 = 0.0f;
#pragma unroll
        for (int nt = 0; nt < 8; nt++) {
            S[nt][0] = __expf(S[nt][0] - mn0);
            S[nt][1] = __expf(S[nt][1] - mn0);
            S[nt][2] = __expf(S[nt][2] - mn1);
            S[nt][3] = __expf(S[nt][3] - mn1);
            rs0 += S[nt][0] + S[nt][1];
            rs1 += S[nt][2] + S[nt][3];
        }
        rs0 += __shfl_xor_sync(0xffffffffu, rs0, 1);
        rs0 += __shfl_xor_sync(0xffffffffu, rs0, 2);
        rs1 += __shfl_xor_sync(0xffffffffu, rs1, 1);
        rs1 += __shfl_xor_sync(0xffffffffu, rs1, 2);
        l0 = l0 * a0 + rs0;
        l1 = l1 * a1 + rs1;
        m0 = mn0; m1 = mn1;
#pragma unroll
        for (int i = 0; i < 16; i++) {
            O[i][0] *= a0; O[i][1] *= a0; O[i][2] *= a1; O[i][3] *= a1;
        }

        // ---- P c-frags -> a-frags (hi/lo split) ----
        uint32_t pa_h[4][4], pa_l[4][4];
#pragma unroll
        for (int ks = 0; ks < 4; ks++) {
            splitpk(S[2 * ks][0],     S[2 * ks][1],     pa_h[ks][0], pa_l[ks][0]);
            splitpk(S[2 * ks][2],     S[2 * ks][3],     pa_h[ks][1], pa_l[ks][1]);
            splitpk(S[2 * ks + 1][0], S[2 * ks + 1][1], pa_h[ks][2], pa_l[ks][2]);
            splitpk(S[2 * ks + 1][2], S[2 * ks + 1][3], pa_h[ks][3], pa_l[ks][3]);
        }

        // ---- O += P . V ----
#pragma unroll
        for (int ks = 0; ks < 4; ks++) {
            const uint32_t va = ((uint32_t)(16 * ks + lm) * FST) * 2 + lk2 * 16;
#pragma unroll
            for (int ntp = 0; ntp < 8; ntp++) {
                uint32_t vv[4], vl4[4];
                LDSM4T(vv,  vh32 + va + ntp * 32);
                LDSM4T(vl4, vl32 + va + ntp * 32);
                uint32_t b0[2] = {vv[0], vv[1]},  b1[2] = {vv[2], vv[3]};
                uint32_t c0[2] = {vl4[0], vl4[1]}, c1[2] = {vl4[2], vl4[3]};
                mma16816(O[2 * ntp],     pa_h[ks], b0);
                mma16816(O[2 * ntp + 1], pa_h[ks], b1);
                mma16816(O[2 * ntp],     pa_l[ks], b0);
                mma16816(O[2 * ntp + 1], pa_l[ks], b1);
                mma16816(O[2 * ntp],     pa_h[ks], c0);
                mma16816(O[2 * ntp + 1], pa_h[ks], c1);
            }
        }
    }

    // ---- epilogue: normalize, split, store in-place over Q split buffers ----
    float il0 = 1.0f / l0, il1 = 1.0f / l1;
    size_t r0 = (size_t)(b * Ss + q0 + wrow + lr) * Dd + h * HDd;
    size_t r1 = r0 + 8 * (size_t)Dd;
#pragma unroll
    for (int nt = 0; nt < 16; nt++) {
        int cc = nt * 8 + lc * 2;
        uint32_t h0, lo0, h1, lo1;
        splitpk(O[nt][0] * il0, O[nt][1] * il0, h0, lo0);
        splitpk(O[nt][2] * il1, O[nt][3] * il1, h1, lo1);
        *(uint32_t*)(Oh + r0 + cc) = h0; *(uint32_t*)(Ol + r0 + cc) = lo0;
        *(uint32_t*)(Oh + r1 + cc) = h1; *(uint32_t*)(Ol + r1 + cc) = lo1;
    }
}

// ---------------- launch ----------------------------------------------------
extern "C" void kernel_launch(void* const* d_in, const int* in_sizes, int n_in,
                              void* d_out, int out_size) {
    const float* x    = (const float*)d_in[0];
    const float* Wq   = (const float*)d_in[1];
    const float* Wk   = (const float*)d_in[2];
    const float* Wv   = (const float*)d_in[3];
    const float* Wp   = (const float*)d_in[4];
    const float* gain = (const float*)d_in[5];
    float* out = (float*)d_out;

    float* qkv;
    bf16 *xh, *xl, *wh, *wl, *kh, *kl, *vh, *vl;
    cudaGetSymbolAddress((void**)&qkv, g_qkv);
    cudaGetSymbolAddress((void**)&xh, g_xh);
    cudaGetSymbolAddress((void**)&xl, g_xl);
    cudaGetSymbolAddress((void**)&wh, g_wh);
    cudaGetSymbolAddress((void**)&wl, g_wl);
    cudaGetSymbolAddress((void**)&kh, g_kh);
    cudaGetSymbolAddress((void**)&kl, g_kl);
    cudaGetSymbolAddress((void**)&vh, g_vh);
    cudaGetSymbolAddress((void**)&vl, g_vl);

    cudaFuncSetAttribute(gemm_bf16s, cudaFuncAttributeMaxDynamicSharedMemorySize, GEMM_SMEM);
    cudaFuncSetAttribute(flash2,     cudaFuncAttributeMaxDynamicSharedMemorySize, FL2_SMEM);

    const int M = Bb * Ss;                 // 4096
    const int n4x = M * Dd / 4;
    const int n4w = Dd * Dd / 4;
    const int n4k = 512 * Dd / 4;

    rope_table_kernel<<<(Ss * 64 + 255) / 256, 256>>>();

    cvt_split<<<(n4x + 255) / 256, 256>>>(x, xh, xl, n4x);

    // fused weight: rows 0-2047 Wq, 2048-2559 Wk, 2560-3071 Wv
    cvt_split<<<(n4w + 255) / 256, 256>>>(Wq, wh, wl, n4w);
    cvt_split<<<(n4k + 255) / 256, 256>>>(Wk, wh + (size_t)2048 * Dd, wl + (size_t)2048 * Dd, n4k);
    cvt_split<<<(n4k + 255) / 256, 256>>>(Wv, wh + (size_t)2560 * Dd, wl + (size_t)2560 * Dd, n4k);

    gemm_bf16s<<<dim3(NQKV / 128, M / 128), 256, GEMM_SMEM>>>(xh, xl, wh, wl, qkv, M, NQKV, Dd);

    q_post<<<(Bb * Ss * Hh) / 8, 256>>>(gain, xh, xl);
    kv_post<<<(Bb * Ss * KVHh) / 8, 256>>>(kh, kl, vh, vl);

    flash2<<<dim3(Ss / FBM, Hh, Bb), 256, FL2_SMEM>>>(xh, xl, kh, kl, vh, vl, xh, xl);

    cvt_split<<<(n4w + 255) / 256, 256>>>(Wp, wh, wl, n4w);
    gemm_bf16s<<<dim3(Dd / 128, M / 128), 256, GEMM_SMEM>>>(xh, xl, wh, wl, out, M, Dd, Dd);
}

// round 10
// speedup vs baseline: 1.5291x; 1.5291x over previous
#include <cuda_runtime.h>
#include <cuda_bf16.h>
#include <math.h>
#include <stdint.h>

#define Bb   2
#define Ss   2048
#define Dd   2048
#define Hh   16
#define KVHh 4
#define HDd  128
#define NQKV 3072      // 2048 q + 512 k + 512 v

typedef __nv_bfloat16 bf16;

// ---------------- scratch (static device globals; no allocs) ----------------
__device__ float g_qkv[Bb * Ss * NQKV];        // fused qkv proj output, 50 MB
__device__ float g_cos[Ss * 64];
__device__ float g_sin[Ss * 64];
// split-bf16 operands. xh/xl: x-split -> Q-split (post) -> attn-out-split (flash)
__device__ __align__(16) bf16 g_xh[Bb * Ss * Dd];
__device__ __align__(16) bf16 g_xl[Bb * Ss * Dd];
__device__ __align__(16) bf16 g_wh[NQKV * Dd];
__device__ __align__(16) bf16 g_wl[NQKV * Dd];
__device__ __align__(16) bf16 g_kh[Bb * Ss * KVHh * HDd];
__device__ __align__(16) bf16 g_kl[Bb * Ss * KVHh * HDd];
__device__ __align__(16) bf16 g_vh[Bb * Ss * KVHh * HDd];
__device__ __align__(16) bf16 g_vl[Bb * Ss * KVHh * HDd];

// ---------------- helpers ----------------------------------------------------
__device__ __forceinline__ uint32_t smem_u32(const void* p) {
    uint32_t a;
    asm("{ .reg .u64 t; cvta.to.shared.u64 t, %1; cvt.u32.u64 %0, t; }" : "=r"(a) : "l"(p));
    return a;
}
#define CP_ASYNC16(dst, src) \
    asm volatile("cp.async.cg.shared.global [%0], [%1], 16;" :: "r"(dst), "l"(src) : "memory")
#define CP_COMMIT()  asm volatile("cp.async.commit_group;" ::: "memory")
#define CP_WAIT1()   asm volatile("cp.async.wait_group 1;" ::: "memory")
#define CP_WAIT0()   asm volatile("cp.async.wait_group 0;" ::: "memory")

__device__ __forceinline__ void mma16816(float* d, const uint32_t* a, const uint32_t* b) {
    asm volatile("mma.sync.aligned.m16n8k16.row.col.f32.bf16.bf16.f32 "
        "{%0,%1,%2,%3}, {%4,%5,%6,%7}, {%8,%9}, {%0,%1,%2,%3};"
        : "+f"(d[0]), "+f"(d[1]), "+f"(d[2]), "+f"(d[3])
        : "r"(a[0]), "r"(a[1]), "r"(a[2]), "r"(a[3]), "r"(b[0]), "r"(b[1]));
}
__device__ __forceinline__ void ldsm4(uint32_t* r, uint32_t a) {
    asm volatile("ldmatrix.sync.aligned.m8n8.x4.shared.b16 {%0,%1,%2,%3}, [%4];"
        : "=r"(r[0]), "=r"(r[1]), "=r"(r[2]), "=r"(r[3]) : "r"(a));
}
#define LDSM4T(r, a) \
    asm volatile("ldmatrix.sync.aligned.m8n8.x4.trans.shared.b16 {%0,%1,%2,%3}, [%4];" \
        : "=r"((r)[0]), "=r"((r)[1]), "=r"((r)[2]), "=r"((r)[3]) : "r"(a))

// pack two fp32 into bf16x2 (hi) and their residuals into bf16x2 (lo)
__device__ __forceinline__ void splitpk(float x0, float x1, uint32_t& hi, uint32_t& lo) {
    bf16 h0 = __float2bfloat16(x0), h1 = __float2bfloat16(x1);
    __nv_bfloat162 th = __halves2bfloat162(h0, h1);
    hi = *(uint32_t*)&th;
    bf16 r0 = __float2bfloat16(x0 - __bfloat162float(h0));
    bf16 r1 = __float2bfloat16(x1 - __bfloat162float(h1));
    __nv_bfloat162 tl = __halves2bfloat162(r0, r1);
    lo = *(uint32_t*)&tl;
}

// ---------------- RoPE table ------------------------------------------------
__global__ void rope_table_kernel() {
    int i = blockIdx.x * blockDim.x + threadIdx.x;
    if (i >= Ss * 64) return;
    int s = i >> 6, j = i & 63;
    float e   = (float)(2 * j) / (float)HDd;
    float inv = 1.0f / powf(10000.0f, e);
    float ang = (float)s * inv;
    g_cos[i] = (float)cos((double)ang);
    g_sin[i] = (float)sin((double)ang);
}

// ---------------- fp32 -> bf16 hi/lo split ----------------------------------
__global__ __launch_bounds__(256) void cvt_split(const float* __restrict__ src,
                                                 bf16* __restrict__ hi,
                                                 bf16* __restrict__ lo, int n4) {
    int i = blockIdx.x * blockDim.x + threadIdx.x;
    if (i >= n4) return;
    float4 v = ((const float4*)src)[i];
    uint32_t h0, l0, h1, l1;
    splitpk(v.x, v.y, h0, l0);
    splitpk(v.z, v.w, h1, l1);
    ((uint32_t*)hi)[2 * i] = h0; ((uint32_t*)hi)[2 * i + 1] = h1;
    ((uint32_t*)lo)[2 * i] = l0; ((uint32_t*)lo)[2 * i + 1] = l1;
}

// ---------------- split-bf16 HMMA GEMM: C = A @ B^T -------------------------
// A:[M,K], B:[N,K] row-major bf16 hi/lo. CTA tile 128x128, K-chunk 32,
// 8 warps 2(M)x4(N), warp tile 64x32. R8 skeleton; ldmatrix frags + 3 passes.
#define LDA        40
#define ARRB       (128 * LDA * 2)          // 10240 B per operand array
#define STAGEB     (4 * ARRB)               // 40960 B per stage
#define GEMM_SMEM  (2 * STAGEB)             // 81920 B

__device__ __forceinline__ void gemm_load_chunk(
    uint32_t sm32, int buf, int tid, int c,
    const bf16* __restrict__ Ah, const bf16* __restrict__ Al,
    const bf16* __restrict__ Bh, const bf16* __restrict__ Bl,
    int bm, int bn, int K) {
    int row = tid >> 2;
    int t16 = tid & 3;
    uint32_t so = sm32 + buf * STAGEB + (uint32_t)row * 80 + (uint32_t)t16 * 16;
    size_t gA = (size_t)(bm + row) * K + (size_t)c * 32 + t16 * 8;
    size_t gB = (size_t)(bn + row) * K + (size_t)c * 32 + t16 * 8;
    size_t stp = (size_t)64 * K;
    CP_ASYNC16(so,                       Ah + gA);
    CP_ASYNC16(so + 64 * 80,             Ah + gA + stp);
    CP_ASYNC16(so + ARRB,                Al + gA);
    CP_ASYNC16(so + ARRB + 64 * 80,      Al + gA + stp);
    CP_ASYNC16(so + 2 * ARRB,            Bh + gB);
    CP_ASYNC16(so + 2 * ARRB + 64 * 80,  Bh + gB + stp);
    CP_ASYNC16(so + 3 * ARRB,            Bl + gB);
    CP_ASYNC16(so + 3 * ARRB + 64 * 80,  Bl + gB + stp);
}

__global__ __launch_bounds__(256, 2) void gemm_bf16s(
    const bf16* __restrict__ Ah, const bf16* __restrict__ Al,
    const bf16* __restrict__ Bh, const bf16* __restrict__ Bl,
    float* __restrict__ C, int M, int N, int K) {
    extern __shared__ char sm[];
    const uint32_t sm32 = smem_u32(sm);
    const int tid  = threadIdx.x;
    const int wid  = tid >> 5, lane = tid & 31;
    const int lr   = lane >> 2, lc = lane & 3;
    const int lm   = lane & 15, lk2 = lane >> 4;
    const int wm   = wid & 1;
    const int wn   = wid >> 1;
    const int bm = blockIdx.y * 128, bn = blockIdx.x * 128;

    float acc[4][4][4];
#pragma unroll
    for (int i = 0; i < 4; i++)
#pragma unroll
        for (int j = 0; j < 4; j++)
#pragma unroll
            for (int r = 0; r < 4; r++) acc[i][j][r] = 0.0f;

    const int NC = K >> 5;
    gemm_load_chunk(sm32, 0, tid, 0, Ah, Al, Bh, Bl, bm, bn, K);
    CP_COMMIT();

    for (int c = 0; c < NC; c++) {
        const int buf = c & 1;
        if (c + 1 < NC) {
            gemm_load_chunk(sm32, buf ^ 1, tid, c + 1, Ah, Al, Bh, Bl, bm, bn, K);
            CP_COMMIT();
            CP_WAIT1();
        } else {
            CP_WAIT0();
        }
        __syncthreads();

        const uint32_t sbase = sm32 + buf * STAGEB;
        const uint32_t aad = sbase + (uint32_t)(wm * 64 + lm) * 80 + lk2 * 16;
        const uint32_t bad = sbase + 2 * ARRB + (uint32_t)(wn * 32 + lm) * 80 + lk2 * 16;
#pragma unroll
        for (int kst = 0; kst < 2; kst++) {
            const uint32_t ko = kst * 32;
            uint32_t ah[4][4], al[4][4], bh[2][4], bl[2][4];
#pragma unroll
            for (int mt = 0; mt < 4; mt++) {
                ldsm4(ah[mt], aad + mt * 1280 + ko);
                ldsm4(al[mt], aad + ARRB + mt * 1280 + ko);
            }
#pragma unroll
            for (int p = 0; p < 2; p++) ldsm4(bh[p], bad + p * 1280 + ko);
            // pass 1: Ah*Bh
#pragma unroll
            for (int mt = 0; mt < 4; mt++)
#pragma unroll
                for (int nt = 0; nt < 4; nt++) {
                    uint32_t bf[2] = { bh[nt >> 1][nt & 1], bh[nt >> 1][(nt & 1) + 2] };
                    mma16816(acc[mt][nt], ah[mt], bf);
                }
            // pass 2: Al*Bh (bh still live)
#pragma unroll
            for (int mt = 0; mt < 4; mt++)
#pragma unroll
                for (int nt = 0; nt < 4; nt++) {
                    uint32_t bf[2] = { bh[nt >> 1][nt & 1], bh[nt >> 1][(nt & 1) + 2] };
                    mma16816(acc[mt][nt], al[mt], bf);
                }
#pragma unroll
            for (int p = 0; p < 2; p++) ldsm4(bl[p], bad + ARRB + p * 1280 + ko);
            // pass 3: Ah*Bl
#pragma unroll
            for (int mt = 0; mt < 4; mt++)
#pragma unroll
                for (int nt = 0; nt < 4; nt++) {
                    uint32_t bf[2] = { bl[nt >> 1][nt & 1], bl[nt >> 1][(nt & 1) + 2] };
                    mma16816(acc[mt][nt], ah[mt], bf);
                }
        }
        __syncthreads();
    }

#pragma unroll
    for (int mt = 0; mt < 4; mt++) {
        int m = bm + wm * 64 + mt * 16 + lr;
#pragma unroll
        for (int nt = 0; nt < 4; nt++) {
            int n = bn + wn * 32 + nt * 8 + lc * 2;
            *(float2*)(C + (size_t)m * N + n)       = make_float2(acc[mt][nt][0], acc[mt][nt][1]);
            *(float2*)(C + (size_t)(m + 8) * N + n) = make_float2(acc[mt][nt][2], acc[mt][nt][3]);
        }
    }
}

// ---------------- q/kv epilogues: RMSNorm + RoPE (+gain) -> bf16 hi/lo ------
__global__ __launch_bounds__(256) void q_post(const float* __restrict__ gain,
                                              bf16* __restrict__ qh, bf16* __restrict__ ql) {
    int wid  = blockIdx.x * 8 + (threadIdx.x >> 5);   // 0..B*S*H-1
    int lane = threadIdx.x & 31;
    int h = wid & (Hh - 1);
    int row = wid >> 4;
    int s = row & (Ss - 1);
    const float* base = g_qkv + (size_t)row * NQKV + h * HDd;
    float e0 = base[lane], e1 = base[lane + 32], e2 = base[lane + 64], e3 = base[lane + 96];
    float ssum = e0 * e0 + e1 * e1 + e2 * e2 + e3 * e3;
#pragma unroll
    for (int o = 16; o > 0; o >>= 1) ssum += __shfl_xor_sync(0xffffffffu, ssum, o);
    float r = rsqrtf(ssum * (1.0f / 128.0f) + 1e-6f);
    float g = gain[h] * r * 0.08838834764831845f;
    float c0 = g_cos[s * 64 + lane],      sn0 = g_sin[s * 64 + lane];
    float c1 = g_cos[s * 64 + lane + 32], sn1 = g_sin[s * 64 + lane + 32];
    float o0 = ( e0 * c0  + e2 * sn0) * g;
    float o1 = ( e1 * c1  + e3 * sn1) * g;
    float o2 = (-e0 * sn0 + e2 * c0 ) * g;
    float o3 = (-e1 * sn1 + e3 * c1 ) * g;
    size_t off = (size_t)wid * 128;
    bf16 h0 = __float2bfloat16(o0); qh[off + lane]      = h0; ql[off + lane]      = __float2bfloat16(o0 - __bfloat162float(h0));
    bf16 h1 = __float2bfloat16(o1); qh[off + lane + 32] = h1; ql[off + lane + 32] = __float2bfloat16(o1 - __bfloat162float(h1));
    bf16 h2 = __float2bfloat16(o2); qh[off + lane + 64] = h2; ql[off + lane + 64] = __float2bfloat16(o2 - __bfloat162float(h2));
    bf16 h3 = __float2bfloat16(o3); qh[off + lane + 96] = h3; ql[off + lane + 96] = __float2bfloat16(o3 - __bfloat162float(h3));
}

__global__ __launch_bounds__(256) void kv_post(bf16* __restrict__ kh, bf16* __restrict__ kl,
                                               bf16* __restrict__ vh, bf16* __restrict__ vl) {
    int wid  = blockIdx.x * 8 + (threadIdx.x >> 5);   // 0..B*S*KVH-1
    int lane = threadIdx.x & 31;
    int kvh = wid & 3;
    int row = wid >> 2;
    int s = row & (Ss - 1);
    const float* kb = g_qkv + (size_t)row * NQKV + 2048 + kvh * HDd;
    const float* vb = kb + 512;
    float e0 = kb[lane], e1 = kb[lane + 32], e2 = kb[lane + 64], e3 = kb[lane + 96];
    float ssum = e0 * e0 + e1 * e1 + e2 * e2 + e3 * e3;
#pragma unroll
    for (int o = 16; o > 0; o >>= 1) ssum += __shfl_xor_sync(0xffffffffu, ssum, o);
    float r = rsqrtf(ssum * (1.0f / 128.0f) + 1e-6f);
    float c0 = g_cos[s * 64 + lane],      sn0 = g_sin[s * 64 + lane];
    float c1 = g_cos[s * 64 + lane + 32], sn1 = g_sin[s * 64 + lane + 32];
    float o0 = ( e0 * c0  + e2 * sn0) * r;
    float o1 = ( e1 * c1  + e3 * sn1) * r;
    float o2 = (-e0 * sn0 + e2 * c0 ) * r;
    float o3 = (-e1 * sn1 + e3 * c1 ) * r;
    size_t off = (size_t)wid * 128;
    bf16 h0 = __float2bfloat16(o0); kh[off + lane]      = h0; kl[off + lane]      = __float2bfloat16(o0 - __bfloat162float(h0));
    bf16 h1 = __float2bfloat16(o1); kh[off + lane + 32] = h1; kl[off + lane + 32] = __float2bfloat16(o1 - __bfloat162float(h1));
    bf16 h2 = __float2bfloat16(o2); kh[off + lane + 64] = h2; kl[off + lane + 64] = __float2bfloat16(o2 - __bfloat162float(h2));
    bf16 h3 = __float2bfloat16(o3); kh[off + lane + 96] = h3; kl[off + lane + 96] = __float2bfloat16(o3 - __bfloat162float(h3));
#pragma unroll
    for (int j = 0; j < 4; j++) {
        float f = vb[lane + 32 * j];
        bf16 fh = __float2bfloat16(f);
        vh[off + lane + 32 * j] = fh;
        vl[off + lane + 32 * j] = __float2bfloat16(f - __bfloat162float(fh));
    }
}

// ---------------- HMMA flash attention (split-bf16, R8-proven, BM=64) -------
#define FST 136
#define FQE (64 * FST)
#define FL2_SMEM ((2 * FQE + 8 * FQE) * 2)   // 174080 bytes

__device__ __forceinline__ void fl_load_kv(uint32_t sbase, int tid, int b, int kvh, int k0,
    const bf16* __restrict__ Kh, const bf16* __restrict__ Kl,
    const bf16* __restrict__ Vh, const bf16* __restrict__ Vl) {
#pragma unroll
    for (int it = 0; it < 8; it++) {
        int c = tid + it * 128;
        int r = c >> 4, o16 = c & 15;
        uint32_t d = sbase + (uint32_t)r * (FST * 2) + o16 * 16;
        size_t g = ((size_t)((b * Ss + k0 + r) * KVHh + kvh)) * HDd + o16 * 8;
        CP_ASYNC16(d,               Kh + g);
        CP_ASYNC16(d + 2 * FQE,     Kl + g);
        CP_ASYNC16(d + 4 * FQE,     Vh + g);
        CP_ASYNC16(d + 6 * FQE,     Vl + g);
    }
}

__global__ __launch_bounds__(128) void flash2(
    const bf16* __restrict__ Qh, const bf16* __restrict__ Ql,
    const bf16* __restrict__ Kh, const bf16* __restrict__ Kl,
    const bf16* __restrict__ Vh, const bf16* __restrict__ Vl,
    bf16* __restrict__ Oh, bf16* __restrict__ Ol) {
    extern __shared__ bf16 smb[];
    bf16* sQh = smb;
    bf16* sQl = smb + FQE;
    const uint32_t sm32 = smem_u32(smb);
    const int tid = threadIdx.x, wid = tid >> 5, lane = tid & 31;
    const int lr = lane >> 2, lc = lane & 3;
    const int qt = (Ss / 64 - 1) - blockIdx.x;
    const int h = blockIdx.y, b = blockIdx.z, kvh = h >> 2;
    const int q0 = qt * 64;
    const int wrow = wid * 16;

#pragma unroll
    for (int it = 0; it < 8; it++) {
        int c = tid + it * 128;
        int r = c >> 4, o = (c & 15) * 8;
        size_t g = (size_t)(b * Ss + q0 + r) * Dd + h * HDd + o;
        *(uint4*)(sQh + r * FST + o) = *(const uint4*)(Qh + g);
        *(uint4*)(sQl + r * FST + o) = *(const uint4*)(Ql + g);
    }
    fl_load_kv(sm32 + 4 * FQE, tid, b, kvh, 0, Kh, Kl, Vh, Vl);
    CP_COMMIT();

    float m0 = -1e30f, m1 = -1e30f, l0 = 0.0f, l1 = 0.0f;
    float O[16][4];
#pragma unroll
    for (int i = 0; i < 16; i++) { O[i][0] = O[i][1] = O[i][2] = O[i][3] = 0.0f; }

    for (int kt = 0; kt <= qt; kt++) {
        const int stage = kt & 1;
        if (kt < qt) {
            fl_load_kv(sm32 + 4 * FQE + (stage ^ 1) * 8 * FQE, tid, b, kvh, (kt + 1) * 64,
                       Kh, Kl, Vh, Vl);
            CP_COMMIT();
            CP_WAIT1();
        } else {
            CP_WAIT0();
        }
        __syncthreads();

        const bf16* sKh = smb + 2 * FQE + stage * 4 * FQE;
        const bf16* sKl = sKh + FQE;
        const uint32_t vh32 = sm32 + (2 * FQE + stage * 4 * FQE + 2 * FQE) * 2;
        const uint32_t vl32 = vh32 + 2 * FQE;

        float S[8][4];
#pragma unroll
        for (int nt = 0; nt < 8; nt++) S[nt][0] = S[nt][1] = S[nt][2] = S[nt][3] = 0.0f;

#pragma unroll
        for (int kst = 0; kst < 8; kst++) {
            const int pp2 = kst * 16 + lc * 2;
            const int r0 = wrow + lr;
            uint32_t qa_h[4], qa_l[4];
            qa_h[0] = *(const uint32_t*)(sQh + r0 * FST + pp2);
            qa_h[1] = *(const uint32_t*)(sQh + (r0 + 8) * FST + pp2);
            qa_h[2] = *(const uint32_t*)(sQh + r0 * FST + pp2 + 8);
            qa_h[3] = *(const uint32_t*)(sQh + (r0 + 8) * FST + pp2 + 8);
            qa_l[0] = *(const uint32_t*)(sQl + r0 * FST + pp2);
            qa_l[1] = *(const uint32_t*)(sQl + (r0 + 8) * FST + pp2);
            qa_l[2] = *(const uint32_t*)(sQl + r0 * FST + pp2 + 8);
            qa_l[3] = *(const uint32_t*)(sQl + (r0 + 8) * FST + pp2 + 8);
#pragma unroll
            for (int nt = 0; nt < 8; nt++) {
                const int n0 = nt * 8 + lr;
                uint32_t kb[2], klb[2];
                kb[0]  = *(const uint32_t*)(sKh + n0 * FST + pp2);
                kb[1]  = *(const uint32_t*)(sKh + n0 * FST + pp2 + 8);
                klb[0] = *(const uint32_t*)(sKl + n0 * FST + pp2);
                klb[1] = *(const uint32_t*)(sKl + n0 * FST + pp2 + 8);
                mma16816(S[nt], qa_h, kb);
                mma16816(S[nt], qa_h, klb);
                mma16816(S[nt], qa_l, kb);
            }
        }

        if (kt == qt) {
            const int row0 = q0 + wrow + lr;
#pragma unroll
            for (int nt = 0; nt < 8; nt++) {
                const int col = kt * 64 + nt * 8 + lc * 2;
                if (col     > row0)     S[nt][0] = -1e30f;
                if (col + 1 > row0)     S[nt][1] = -1e30f;
                if (col     > row0 + 8) S[nt][2] = -1e30f;
                if (col + 1 > row0 + 8) S[nt][3] = -1e30f;
            }
        }

        float rm0 = -1e30f, rm1 = -1e30f;
#pragma unroll
        for (int nt = 0; nt < 8; nt++) {
            rm0 = fmaxf(rm0, fmaxf(S[nt][0], S[nt][1]));
            rm1 = fmaxf(rm1, fmaxf(S[nt][2], S[nt][3]));
        }
        rm0 = fmaxf(rm0, __shfl_xor_sync(0xffffffffu, rm0, 1));
        rm0 = fmaxf(rm0, __shfl_xor_sync(0xffffffffu, rm0, 2));
        rm1 = fmaxf(rm1, __shfl_xor_sync(0xffffffffu, rm1, 1));
        rm1 = fmaxf(rm1, __shfl_xor_sync(0xffffffffu, rm1, 2));
        float mn0 = fmaxf(m0, rm0), mn1 = fmaxf(m1, rm1);
        float a0 = __expf(m0 - mn0), a1 = __expf(m1 - mn1);
        float rs0 = 0.0f, rs1 = 0.0f;
#pragma unroll
        for (int nt = 0; nt < 8; nt++) {
            S[nt][0] = __expf(S[nt][0] - mn0);
            S[nt][1] = __expf(S[nt][1] - mn0);
            S[nt][2] = __expf(S[nt][2] - mn1);
            S[nt][3] = __expf(S[nt][3] - mn1);
            rs0 += S[nt][0] + S[nt][1];
            rs1 += S[nt][2] + S[nt][3];
        }
        rs0 += __shfl_xor_sync(0xffffffffu, rs0, 1);
        rs0 += __shfl_xor_sync(0xffffffffu, rs0, 2);
        rs1 += __shfl_xor_sync(0xffffffffu, rs1, 1);
        rs1 += __shfl_xor_sync(0xffffffffu, rs1, 2);
        l0 = l0 * a0 + rs0;
        l1 = l1 * a1 + rs1;
        m0 = mn0; m1 = mn1;
#pragma unroll
        for (int i = 0; i < 16; i++) {
            O[i][0] *= a0; O[i][1] *= a0; O[i][2] *= a1; O[i][3] *= a1;
        }

        uint32_t pa_h[4][4], pa_l[4][4];
#pragma unroll
        for (int ks = 0; ks < 4; ks++) {
            splitpk(S[2 * ks][0],     S[2 * ks][1],     pa_h[ks][0], pa_l[ks][0]);
            splitpk(S[2 * ks][2],     S[2 * ks][3],     pa_h[ks][1], pa_l[ks][1]);
            splitpk(S[2 * ks + 1][0], S[2 * ks + 1][1], pa_h[ks][2], pa_l[ks][2]);
            splitpk(S[2 * ks + 1][2], S[2 * ks + 1][3], pa_h[ks][3], pa_l[ks][3]);
        }

#pragma unroll
        for (int ks = 0; ks < 4; ks++) {
            const uint32_t va = ((uint32_t)(16 * ks + (lane & 15)) * FST) * 2 + (lane >> 4) * 16;
#pragma unroll
            for (int ntp = 0; ntp < 8; ntp++) {
                uint32_t vh4[4], vl4[4];
                LDSM4T(vh4, vh32 + va + ntp * 32);
                LDSM4T(vl4, vl32 + va + ntp * 32);
                uint32_t b0[2] = {vh4[0], vh4[1]}, b1[2] = {vh4[2], vh4[3]};
                uint32_t c0[2] = {vl4[0], vl4[1]}, c1[2] = {vl4[2], vl4[3]};
                mma16816(O[2 * ntp],     pa_h[ks], b0);
                mma16816(O[2 * ntp],     pa_l[ks], b0);
                mma16816(O[2 * ntp],     pa_h[ks], c0);
                mma16816(O[2 * ntp + 1], pa_h[ks], b1);
                mma16816(O[2 * ntp + 1], pa_l[ks], b1);
                mma16816(O[2 * ntp + 1], pa_h[ks], c1);
            }
        }
        __syncthreads();
    }

    float il0 = 1.0f / l0, il1 = 1.0f / l1;
    size_t r0 = (size_t)(b * Ss + q0 + wrow + lr) * Dd + h * HDd;
    size_t r1 = r0 + 8 * (size_t)Dd;
#pragma unroll
    for (int nt = 0; nt < 16; nt++) {
        int cc = nt * 8 + lc * 2;
        uint32_t h0, lo0, h1, lo1;
        splitpk(O[nt][0] * il0, O[nt][1] * il0, h0, lo0);
        splitpk(O[nt][2] * il1, O[nt][3] * il1, h1, lo1);
        *(uint32_t*)(Oh + r0 + cc) = h0; *(uint32_t*)(Ol + r0 + cc) = lo0;
        *(uint32_t*)(Oh + r1 + cc) = h1; *(uint32_t*)(Ol + r1 + cc) = lo1;
    }
}

// ---------------- launch ----------------------------------------------------
extern "C" void kernel_launch(void* const* d_in, const int* in_sizes, int n_in,
                              void* d_out, int out_size) {
    const float* x    = (const float*)d_in[0];
    const float* Wq   = (const float*)d_in[1];
    const float* Wk   = (const float*)d_in[2];
    const float* Wv   = (const float*)d_in[3];
    const float* Wp   = (const float*)d_in[4];
    const float* gain = (const float*)d_in[5];
    float* out = (float*)d_out;

    float* qkv;
    bf16 *xh, *xl, *wh, *wl, *kh, *kl, *vh, *vl;
    cudaGetSymbolAddress((void**)&qkv, g_qkv);
    cudaGetSymbolAddress((void**)&xh, g_xh);
    cudaGetSymbolAddress((void**)&xl, g_xl);
    cudaGetSymbolAddress((void**)&wh, g_wh);
    cudaGetSymbolAddress((void**)&wl, g_wl);
    cudaGetSymbolAddress((void**)&kh, g_kh);
    cudaGetSymbolAddress((void**)&kl, g_kl);
    cudaGetSymbolAddress((void**)&vh, g_vh);
    cudaGetSymbolAddress((void**)&vl, g_vl);

    cudaFuncSetAttribute(gemm_bf16s, cudaFuncAttributeMaxDynamicSharedMemorySize, GEMM_SMEM);
    cudaFuncSetAttribute(flash2,     cudaFuncAttributeMaxDynamicSharedMemorySize, FL2_SMEM);

    const int M = Bb * Ss;                 // 4096
    const int n4x = M * Dd / 4;
    const int n4w = Dd * Dd / 4;
    const int n4k = 512 * Dd / 4;

    rope_table_kernel<<<(Ss * 64 + 255) / 256, 256>>>();

    cvt_split<<<(n4x + 255) / 256, 256>>>(x, xh, xl, n4x);

    // fused weight: rows 0-2047 Wq, 2048-2559 Wk, 2560-3071 Wv
    cvt_split<<<(n4w + 255) / 256, 256>>>(Wq, wh, wl, n4w);
    cvt_split<<<(n4k + 255) / 256, 256>>>(Wk, wh + (size_t)2048 * Dd, wl + (size_t)2048 * Dd, n4k);
    cvt_split<<<(n4k + 255) / 256, 256>>>(Wv, wh + (size_t)2560 * Dd, wl + (size_t)2560 * Dd, n4k);

    gemm_bf16s<<<dim3(NQKV / 128, M / 128), 256, GEMM_SMEM>>>(xh, xl, wh, wl, qkv, M, NQKV, Dd);

    q_post<<<(Bb * Ss * Hh) / 8, 256>>>(gain, xh, xl);
    kv_post<<<(Bb * Ss * KVHh) / 8, 256>>>(kh, kl, vh, vl);

    flash2<<<dim3(Ss / 64, Hh, Bb), 128, FL2_SMEM>>>(xh, xl, kh, kl, vh, vl, xh, xl);

    cvt_split<<<(n4w + 255) / 256, 256>>>(Wp, wh, wl, n4w);
    gemm_bf16s<<<dim3(Dd / 128, M / 128), 256, GEMM_SMEM>>>(xh, xl, wh, wl, out, M, Dd, Dd);
}